// round 3
// baseline (speedup 1.0000x reference)
#include <cuda_runtime.h>
#include <math.h>

// ---------------- problem constants ----------------
#define BQ     2
#define LQ     1024
#define DQ     256
#define NLQ    4
#define DINQ   512
#define HQ     8
#define PQ     64
#define NSQ    64
#define CONVD  640           // DIN + 2*NSTATE
#define DPROJ  1160          // 2*DIN + 2*NSTATE + H
#define NCH    16            // chunks for scan
#define LC     64            // chunk length (LQ / NCH)

// ---------------- scratch (device globals; no allocation) ----------------
static __device__ float g_x  [BQ*LQ*DQ];
static __device__ float g_zx [BQ*LQ*DPROJ];
static __device__ float g_xBC[BQ*LQ*CONVD];
static __device__ float g_dt [BQ*LQ*HQ];
static __device__ float g_dA [BQ*LQ*HQ];
static __device__ float g_cum[BQ*HQ*LQ];
static __device__ float g_y  [BQ*LQ*DINQ];
static __device__ float g_F  [BQ*HQ*NCH*PQ*NSQ];
static __device__ float g_Hs [BQ*HQ*NCH*PQ*NSQ];
static __device__ float g_pool[BQ*DQ];

__device__ __forceinline__ float geluf(float x){
    return 0.5f * x * (1.0f + erff(x * 0.7071067811865476f));
}

// ---------------- embedding ----------------
__global__ void k_embed(const int* __restrict__ ids, const float* __restrict__ emb,
                        const float* __restrict__ pos){
    int row = blockIdx.x;            // b*LQ + l
    int l   = row & (LQ-1);
    int d   = threadIdx.x;
    g_x[(size_t)row*DQ + d] = emb[(size_t)ids[row]*DQ + d] + pos[(size_t)l*DQ + d];
}

// ---------------- fp32 NT GEMM core: C[m,n] (+)= sum_k A[m,k]*B[n,k] ----------------
template<int M, int N, int K, bool ACC>
__device__ __forceinline__ void gemm_core(const float* __restrict__ A,
                                          const float* __restrict__ Bw,
                                          float* __restrict__ Cc){
    constexpr int BM=64, BN=64;
    __shared__ __align__(16) float As[16][BM];
    __shared__ __align__(16) float Bs[16][BN];
    const int tid = threadIdx.x;
    const int bm  = blockIdx.y * BM;
    const int bn  = blockIdx.x * BN;
    const int tr  = (tid >> 4) << 2;   // 0..60
    const int tc  = (tid & 15) << 2;   // 0..60
    const int lr  = tid >> 2;          // 0..63
    const int lc  = (tid & 3) << 2;    // 0,4,8,12
    float acc[4][4];
    #pragma unroll
    for (int m=0;m<4;m++)
        #pragma unroll
        for (int n=0;n<4;n++) acc[m][n]=0.f;

    const float* Aptr = A  + (size_t)(bm+lr)*K + lc;
    const float* Bptr = Bw + (size_t)(bn+lr)*K + lc;
    const bool bvalid = (N % BN == 0) || (bn + lr < N);

    for (int k0=0; k0<K; k0+=16){
        float4 av = *(const float4*)(Aptr + k0);
        float4 bv = make_float4(0.f,0.f,0.f,0.f);
        if (bvalid) bv = *(const float4*)(Bptr + k0);
        As[lc+0][lr]=av.x; As[lc+1][lr]=av.y; As[lc+2][lr]=av.z; As[lc+3][lr]=av.w;
        Bs[lc+0][lr]=bv.x; Bs[lc+1][lr]=bv.y; Bs[lc+2][lr]=bv.z; Bs[lc+3][lr]=bv.w;
        __syncthreads();
        #pragma unroll
        for (int kk=0; kk<16; kk++){
            float4 ra4 = *(const float4*)&As[kk][tr];
            float4 rb4 = *(const float4*)&Bs[kk][tc];
            float ra[4] = {ra4.x, ra4.y, ra4.z, ra4.w};
            float rb[4] = {rb4.x, rb4.y, rb4.z, rb4.w};
            #pragma unroll
            for (int m=0;m<4;m++)
                #pragma unroll
                for (int n=0;n<4;n++)
                    acc[m][n] = fmaf(ra[m], rb[n], acc[m][n]);
        }
        __syncthreads();
    }
    #pragma unroll
    for (int m=0;m<4;m++){
        int row = bm + tr + m;
        #pragma unroll
        for (int n=0;n<4;n++){
            int col = bn + tc + n;
            if (N % BN == 0 || col < N){
                size_t idx = (size_t)row*N + col;
                if (ACC) Cc[idx] += acc[m][n];
                else     Cc[idx]  = acc[m][n];
            }
        }
    }
}

__global__ __launch_bounds__(256) void k_gemm_in(const float* __restrict__ W){
    gemm_core<BQ*LQ, DPROJ, DQ, false>(g_x, W, g_zx);
}
__global__ __launch_bounds__(256) void k_gemm_out(const float* __restrict__ W){
    gemm_core<BQ*LQ, DQ, DINQ, true>(g_y, W, g_x);
}

// ---------------- depthwise causal conv + SiLU, and dt / dA ----------------
__global__ void k_convdt(const float* __restrict__ cw, const float* __restrict__ cb,
                         const float* __restrict__ dtb, const float* __restrict__ Alog){
    int row = blockIdx.x;            // b*LQ + l
    int l   = row & (LQ-1);
    int ci  = threadIdx.x;           // 0..639
    float4 w = *(const float4*)(cw + ci*4);   // conv_w[ci][0..3]
    const float* src = g_zx + (size_t)row*DPROJ + DINQ + ci;
    float acc = cb[ci];
    acc = fmaf(w.w, src[0], acc);
    if (l >= 1) acc = fmaf(w.z, src[-DPROJ],   acc);
    if (l >= 2) acc = fmaf(w.y, src[-2*DPROJ], acc);
    if (l >= 3) acc = fmaf(w.x, src[-3*DPROJ], acc);
    g_xBC[(size_t)row*CONVD + ci] = acc / (1.f + expf(-acc));   // SiLU
    if (ci < HQ){
        float raw = g_zx[(size_t)row*DPROJ + (DINQ + CONVD) + ci] + dtb[ci];
        float dt  = (raw > 20.f) ? raw : log1pf(expf(raw));     // softplus
        g_dt[(size_t)row*HQ + ci] = dt;
        g_dA[(size_t)row*HQ + ci] = expf(-expf(Alog[ci]) * dt); // exp(dt*A), A=-exp(A_log)
    }
}

// ---------------- SSM scan pass 1: per-chunk local scan (h_start = 0) ----------------
// block = (b, h, chunk); 256 threads: p = tid/4, n-quarter = (tid%4)*16
__global__ __launch_bounds__(256) void k_scan1(){
    const int blk = blockIdx.x;
    const int c   = blk & (NCH-1);
    const int bh  = blk >> 4;
    const int h   = bh & (HQ-1);
    const int b   = bh >> 3;
    const int tid = threadIdx.x;
    const int p   = tid >> 2, q = tid & 3;

    __shared__ __align__(16) float sX[2][PQ];
    __shared__ __align__(16) float sB[2][NSQ];
    __shared__ __align__(16) float sC[2][NSQ];
    __shared__ float sS[2][2];

    float hs[16];
    #pragma unroll
    for (int j=0;j<16;j++) hs[j]=0.f;

    const int t0 = c*LC;
    {   // prologue load (buffer 0)
        const float* rowp = g_xBC + (size_t)(b*LQ + t0)*CONVD;
        if      (tid <  64) sX[0][tid]      = rowp[h*PQ + tid];
        else if (tid < 128) sB[0][tid-64]   = rowp[DINQ + tid-64];
        else if (tid < 192) sC[0][tid-128]  = rowp[DINQ + NSQ + tid-128];
        else if (tid == 192) sS[0][0] = g_dA[(size_t)(b*LQ + t0)*HQ + h];
        else if (tid == 193) sS[0][1] = g_dt[(size_t)(b*LQ + t0)*HQ + h];
    }
    __syncthreads();

    float cprod = 1.f;
    for (int s=0; s<LC; s++){
        const int bf = s & 1;
        const int t  = t0 + s;
        const float dA  = sS[bf][0];
        const float dtx = sS[bf][1] * sX[bf][p];
        const float4* pB = (const float4*)&sB[bf][q*16];
        const float4* pC = (const float4*)&sC[bf][q*16];
        float acc = 0.f;
        #pragma unroll
        for (int v=0; v<4; v++){
            float4 bb = pB[v], cc = pC[v];
            hs[4*v+0] = fmaf(dA, hs[4*v+0], dtx*bb.x); acc = fmaf(hs[4*v+0], cc.x, acc);
            hs[4*v+1] = fmaf(dA, hs[4*v+1], dtx*bb.y); acc = fmaf(hs[4*v+1], cc.y, acc);
            hs[4*v+2] = fmaf(dA, hs[4*v+2], dtx*bb.z); acc = fmaf(hs[4*v+2], cc.z, acc);
            hs[4*v+3] = fmaf(dA, hs[4*v+3], dtx*bb.w); acc = fmaf(hs[4*v+3], cc.w, acc);
        }
        if (s+1 < LC){  // prefetch next step into the other buffer
            const int t2 = t+1, bf2 = bf^1;
            const float* rowp = g_xBC + (size_t)(b*LQ + t2)*CONVD;
            if      (tid <  64) sX[bf2][tid]     = rowp[h*PQ + tid];
            else if (tid < 128) sB[bf2][tid-64]  = rowp[DINQ + tid-64];
            else if (tid < 192) sC[bf2][tid-128] = rowp[DINQ + NSQ + tid-128];
            else if (tid == 192) sS[bf2][0] = g_dA[(size_t)(b*LQ + t2)*HQ + h];
            else if (tid == 193) sS[bf2][1] = g_dt[(size_t)(b*LQ + t2)*HQ + h];
        }
        acc += __shfl_xor_sync(0xffffffffu, acc, 1);
        acc += __shfl_xor_sync(0xffffffffu, acc, 2);
        if (q == 0) g_y[(size_t)(b*LQ + t)*DINQ + h*PQ + p] = acc;
        if (tid == 0){ cprod *= dA; g_cum[(size_t)bh*LQ + t] = cprod; }
        __syncthreads();
    }
    // chunk-final local state
    float4* Fo = (float4*)(g_F + (size_t)blk*(PQ*NSQ) + p*NSQ + q*16);
    Fo[0] = make_float4(hs[0], hs[1], hs[2], hs[3]);
    Fo[1] = make_float4(hs[4], hs[5], hs[6], hs[7]);
    Fo[2] = make_float4(hs[8], hs[9], hs[10], hs[11]);
    Fo[3] = make_float4(hs[12], hs[13], hs[14], hs[15]);
}

// ---------------- chain chunk-start states across chunks ----------------
__global__ __launch_bounds__(256) void k_combine(){
    const int bh  = blockIdx.x;      // 0..15
    const int tid = threadIdx.x;     // owns 16 contiguous state elems
    float hs[16];
    #pragma unroll
    for (int j=0;j<16;j++) hs[j]=0.f;
    for (int c=0; c<NCH; c++){
        size_t base = ((size_t)bh*NCH + c)*(PQ*NSQ) + (size_t)tid*16;
        float4* Ho = (float4*)(g_Hs + base);
        const float4* Fi = (const float4*)(g_F + base);
        float Pt = g_cum[(size_t)bh*LQ + c*LC + (LC-1)];
        #pragma unroll
        for (int v=0; v<4; v++){
            Ho[v] = make_float4(hs[4*v+0], hs[4*v+1], hs[4*v+2], hs[4*v+3]);
            float4 f = Fi[v];
            hs[4*v+0] = fmaf(Pt, hs[4*v+0], f.x);
            hs[4*v+1] = fmaf(Pt, hs[4*v+1], f.y);
            hs[4*v+2] = fmaf(Pt, hs[4*v+2], f.z);
            hs[4*v+3] = fmaf(Pt, hs[4*v+3], f.w);
        }
    }
}

// ---------------- scan pass 2: y += cum_t * (C_t . h_start) + D * x ----------------
__global__ __launch_bounds__(256) void k_scan2(const float* __restrict__ Dparam){
    const int blk = blockIdx.x;
    const int c   = blk & (NCH-1);
    const int bh  = blk >> 4;
    const int h   = bh & (HQ-1);
    const int b   = bh >> 3;
    const int tid = threadIdx.x;
    const int p   = tid >> 2, q = tid & 3;

    __shared__ __align__(16) float sC[2][NSQ];
    __shared__ float sX[2][PQ];
    __shared__ float sM[2];

    const float4* Hi = (const float4*)(g_Hs + (size_t)blk*(PQ*NSQ) + p*NSQ + q*16);
    float4 h0 = Hi[0], h1 = Hi[1], h2 = Hi[2], h3 = Hi[3];
    const float Dv = Dparam[h];
    const int t0 = c*LC;
    {
        const float* rowp = g_xBC + (size_t)(b*LQ + t0)*CONVD;
        if      (tid <  64) sC[0][tid]    = rowp[DINQ + NSQ + tid];
        else if (tid < 128) sX[0][tid-64] = rowp[h*PQ + tid-64];
        else if (tid == 128) sM[0] = g_cum[(size_t)bh*LQ + t0];
    }
    __syncthreads();

    for (int s=0; s<LC; s++){
        const int bf = s & 1;
        const int t  = t0 + s;
        const float4* pC = (const float4*)&sC[bf][q*16];
        float4 c0=pC[0], c1=pC[1], c2=pC[2], c3=pC[3];
        float acc = 0.f;
        acc = fmaf(h0.x,c0.x,acc); acc = fmaf(h0.y,c0.y,acc); acc = fmaf(h0.z,c0.z,acc); acc = fmaf(h0.w,c0.w,acc);
        acc = fmaf(h1.x,c1.x,acc); acc = fmaf(h1.y,c1.y,acc); acc = fmaf(h1.z,c1.z,acc); acc = fmaf(h1.w,c1.w,acc);
        acc = fmaf(h2.x,c2.x,acc); acc = fmaf(h2.y,c2.y,acc); acc = fmaf(h2.z,c2.z,acc); acc = fmaf(h2.w,c2.w,acc);
        acc = fmaf(h3.x,c3.x,acc); acc = fmaf(h3.y,c3.y,acc); acc = fmaf(h3.z,c3.z,acc); acc = fmaf(h3.w,c3.w,acc);
        float cm = sM[bf];
        float xv = sX[bf][p];
        if (s+1 < LC){
            const int t2 = t+1, bf2 = bf^1;
            const float* rowp = g_xBC + (size_t)(b*LQ + t2)*CONVD;
            if      (tid <  64) sC[bf2][tid]    = rowp[DINQ + NSQ + tid];
            else if (tid < 128) sX[bf2][tid-64] = rowp[h*PQ + tid-64];
            else if (tid == 128) sM[bf2] = g_cum[(size_t)bh*LQ + t2];
        }
        acc += __shfl_xor_sync(0xffffffffu, acc, 1);
        acc += __shfl_xor_sync(0xffffffffu, acc, 2);
        if (q == 0){
            size_t idx = (size_t)(b*LQ + t)*DINQ + h*PQ + p;
            g_y[idx] += cm*acc + Dv*xv;
        }
        __syncthreads();
    }
}

// ---------------- gate (SiLU(z)) + RMSNorm ----------------
__global__ __launch_bounds__(512) void k_gatenorm(const float* __restrict__ nw){
    int row = blockIdx.x;
    int tid = threadIdx.x;
    float y = g_y[(size_t)row*DINQ + tid];
    float z = g_zx[(size_t)row*DPROJ + tid];
    float v = y * (z / (1.f + expf(-z)));
    float ss = v*v;
    #pragma unroll
    for (int o=16;o;o>>=1) ss += __shfl_xor_sync(0xffffffffu, ss, o);
    __shared__ float red[16];
    if ((tid & 31) == 0) red[tid>>5] = ss;
    __syncthreads();
    if (tid < 32){
        float t = (tid < 16) ? red[tid] : 0.f;
        #pragma unroll
        for (int o=8;o;o>>=1) t += __shfl_xor_sync(0xffffffffu, t, o);
        if (tid == 0) red[0] = t;
    }
    __syncthreads();
    float r = rsqrtf(red[0]*(1.f/DINQ) + 1e-5f);
    g_y[(size_t)row*DINQ + tid] = v * r * nw[tid];
}

// ---------------- pooling: (mean_l + max_l) * 0.5 ----------------
__global__ void k_pool(){
    int b = blockIdx.x, d = threadIdx.x;
    const float* base = g_x + (size_t)b*LQ*DQ + d;
    float s = 0.f, m = -3.4e38f;
    #pragma unroll 8
    for (int l=0; l<LQ; l++){
        float v = base[(size_t)l*DQ];
        s += v; m = fmaxf(m, v);
    }
    g_pool[b*DQ + d] = (s*(1.f/LQ) + m)*0.5f;
}

// ---------------- classification head (single block) ----------------
__global__ __launch_bounds__(256) void k_head(const float* __restrict__ pw, const float* __restrict__ pb,
                                              const float* __restrict__ c1w, const float* __restrict__ c1b,
                                              const float* __restrict__ c2w, const float* __restrict__ c2b,
                                              float* __restrict__ out){
    __shared__ __align__(16) float sp[BQ*DQ];
    __shared__ __align__(16) float h1[BQ*DQ];
    __shared__ __align__(16) float h2[BQ*128];
    int tid = threadIdx.x;
    for (int i=tid; i<BQ*DQ; i+=256) sp[i] = g_pool[i];
    __syncthreads();
    // pooler: 512 outputs, gelu
    for (int i=tid; i<BQ*DQ; i+=256){
        int b = i >> 8, o = i & 255;
        const float4* xr = (const float4*)(sp + b*DQ);
        const float4* wr = (const float4*)(pw + (size_t)o*DQ);
        float a = pb[o];
        #pragma unroll 8
        for (int k=0; k<DQ/4; k++){
            float4 xv = xr[k], wv = wr[k];
            a = fmaf(xv.x,wv.x,a); a = fmaf(xv.y,wv.y,a);
            a = fmaf(xv.z,wv.z,a); a = fmaf(xv.w,wv.w,a);
        }
        h1[i] = geluf(a);
    }
    __syncthreads();
    // cls1: 256 outputs, gelu
    {
        int b = tid >> 7, o = tid & 127;
        const float4* xr = (const float4*)(h1 + b*DQ);
        const float4* wr = (const float4*)(c1w + (size_t)o*DQ);
        float a = c1b[o];
        #pragma unroll 8
        for (int k=0; k<DQ/4; k++){
            float4 xv = xr[k], wv = wr[k];
            a = fmaf(xv.x,wv.x,a); a = fmaf(xv.y,wv.y,a);
            a = fmaf(xv.z,wv.z,a); a = fmaf(xv.w,wv.w,a);
        }
        h2[tid] = geluf(a);
    }
    __syncthreads();
    // cls2: 4 outputs
    if (tid < 4){
        int b = tid >> 1, o = tid & 1;
        const float* xr = h2 + b*128;
        const float* wr = c2w + o*128;
        float a = c2b[o];
        #pragma unroll 8
        for (int k=0; k<128; k++) a = fmaf(xr[k], wr[k], a);
        out[b*2 + o] = a;
    }
}

// ---------------- launcher ----------------
extern "C" void kernel_launch(void* const* d_in, const int* in_sizes, int n_in,
                              void* d_out, int out_size){
    (void)in_sizes; (void)n_in; (void)out_size;
    const int*   ids  = (const int*)  d_in[0];
    const float* emb  = (const float*)d_in[1];
    const float* pos  = (const float*)d_in[2];
    const float* Win  = (const float*)d_in[3];
    const float* cw   = (const float*)d_in[4];
    const float* cb   = (const float*)d_in[5];
    const float* dtb  = (const float*)d_in[6];
    const float* Alog = (const float*)d_in[7];
    const float* Dpar = (const float*)d_in[8];
    const float* nw   = (const float*)d_in[9];
    const float* Wout = (const float*)d_in[10];
    const float* pw   = (const float*)d_in[11];
    const float* pb   = (const float*)d_in[12];
    const float* c1w  = (const float*)d_in[13];
    const float* c1b  = (const float*)d_in[14];
    const float* c2w  = (const float*)d_in[15];
    const float* c2b  = (const float*)d_in[16];
    float* out = (float*)d_out;

    k_embed<<<BQ*LQ, DQ>>>(ids, emb, pos);
    for (int i=0; i<NLQ; i++){
        k_gemm_in <<<dim3((DPROJ+63)/64, (BQ*LQ)/64), 256>>>(Win + (size_t)i*DPROJ*DQ);
        k_convdt  <<<BQ*LQ, CONVD>>>(cw + (size_t)i*CONVD*4, cb + (size_t)i*CONVD,
                                     dtb + (size_t)i*HQ, Alog + (size_t)i*HQ);
        k_scan1   <<<BQ*HQ*NCH, 256>>>();
        k_combine <<<BQ*HQ, 256>>>();
        k_scan2   <<<BQ*HQ*NCH, 256>>>(Dpar + (size_t)i*HQ);
        k_gatenorm<<<BQ*LQ, DINQ>>>(nw + (size_t)i*DINQ);
        k_gemm_out<<<dim3(DQ/64, (BQ*LQ)/64), 256>>>(Wout + (size_t)i*DQ*DINQ);
    }
    k_pool<<<BQ, DQ>>>();
    k_head<<<1, 256>>>(pw, pb, c1w, c1b, c2w, c2b, out);
}

// round 4
// speedup vs baseline: 1.1456x; 1.1456x over previous
#include <cuda_runtime.h>
#include <math.h>

// ---------------- problem constants ----------------
#define BQ     2
#define LQ     1024
#define DQ     256
#define NLQ    4
#define DINQ   512
#define HQ     8
#define PQ     64
#define NSQ    64
#define CONVD  640           // DIN + 2*NSTATE
#define DPROJ  1160          // 2*DIN + 2*NSTATE + H
#define NCH    32            // chunks for scan
#define LC     32            // chunk length (LQ / NCH)
#define SST    8             // time-steps staged per barrier
#define NSTG   (LC/SST)      // stages per chunk

// ---------------- scratch (device globals; no allocation) ----------------
static __device__ float g_x  [BQ*LQ*DQ];
static __device__ float g_zx [BQ*LQ*DPROJ];
static __device__ float g_xBC[BQ*LQ*CONVD];
static __device__ float g_dt [BQ*LQ*HQ];
static __device__ float g_dA [BQ*LQ*HQ];
static __device__ float g_cum[BQ*HQ*LQ];
static __device__ float g_y  [BQ*LQ*DINQ];
static __device__ float g_y2 [BQ*LQ*DINQ];
static __device__ float g_F  [BQ*HQ*NCH*PQ*NSQ];
static __device__ float g_Hs [BQ*HQ*NCH*PQ*NSQ];
static __device__ float g_pool[BQ*DQ];

__device__ __forceinline__ float geluf(float x){
    return 0.5f * x * (1.0f + erff(x * 0.7071067811865476f));
}

// ---------------- embedding ----------------
__global__ void k_embed(const int* __restrict__ ids, const float* __restrict__ emb,
                        const float* __restrict__ pos){
    int row = blockIdx.x;            // b*LQ + l
    int l   = row & (LQ-1);
    int d   = threadIdx.x;
    g_x[(size_t)row*DQ + d] = emb[(size_t)ids[row]*DQ + d] + pos[(size_t)l*DQ + d];
}

// ---------------- fp32 NT GEMM core: C[m,n] (+)= sum_k A[m,k]*B[n,k] ----------------
template<int M, int N, int K, bool ACC>
__device__ __forceinline__ void gemm_core(const float* __restrict__ A,
                                          const float* __restrict__ Bw,
                                          float* __restrict__ Cc){
    constexpr int BM=64, BN=64;
    __shared__ __align__(16) float As[16][BM];
    __shared__ __align__(16) float Bs[16][BN];
    const int tid = threadIdx.x;
    const int bm  = blockIdx.y * BM;
    const int bn  = blockIdx.x * BN;
    const int tr  = (tid >> 4) << 2;   // 0..60
    const int tc  = (tid & 15) << 2;   // 0..60
    const int lr  = tid >> 2;          // 0..63
    const int lc  = (tid & 3) << 2;    // 0,4,8,12
    float acc[4][4];
    #pragma unroll
    for (int m=0;m<4;m++)
        #pragma unroll
        for (int n=0;n<4;n++) acc[m][n]=0.f;

    const float* Aptr = A  + (size_t)(bm+lr)*K + lc;
    const float* Bptr = Bw + (size_t)(bn+lr)*K + lc;
    const bool bvalid = (N % BN == 0) || (bn + lr < N);

    for (int k0=0; k0<K; k0+=16){
        float4 av = *(const float4*)(Aptr + k0);
        float4 bv = make_float4(0.f,0.f,0.f,0.f);
        if (bvalid) bv = *(const float4*)(Bptr + k0);
        As[lc+0][lr]=av.x; As[lc+1][lr]=av.y; As[lc+2][lr]=av.z; As[lc+3][lr]=av.w;
        Bs[lc+0][lr]=bv.x; Bs[lc+1][lr]=bv.y; Bs[lc+2][lr]=bv.z; Bs[lc+3][lr]=bv.w;
        __syncthreads();
        #pragma unroll
        for (int kk=0; kk<16; kk++){
            float4 ra4 = *(const float4*)&As[kk][tr];
            float4 rb4 = *(const float4*)&Bs[kk][tc];
            float ra[4] = {ra4.x, ra4.y, ra4.z, ra4.w};
            float rb[4] = {rb4.x, rb4.y, rb4.z, rb4.w};
            #pragma unroll
            for (int m=0;m<4;m++)
                #pragma unroll
                for (int n=0;n<4;n++)
                    acc[m][n] = fmaf(ra[m], rb[n], acc[m][n]);
        }
        __syncthreads();
    }
    #pragma unroll
    for (int m=0;m<4;m++){
        int row = bm + tr + m;
        #pragma unroll
        for (int n=0;n<4;n++){
            int col = bn + tc + n;
            if (N % BN == 0 || col < N){
                size_t idx = (size_t)row*N + col;
                if (ACC) Cc[idx] += acc[m][n];
                else     Cc[idx]  = acc[m][n];
            }
        }
    }
}

__global__ __launch_bounds__(256) void k_gemm_in(const float* __restrict__ W){
    gemm_core<BQ*LQ, DPROJ, DQ, false>(g_x, W, g_zx);
}
__global__ __launch_bounds__(256) void k_gemm_out(const float* __restrict__ W){
    gemm_core<BQ*LQ, DQ, DINQ, true>(g_y, W, g_x);
}

// ---------------- depthwise causal conv + SiLU, and dt / dA ----------------
__global__ void k_convdt(const float* __restrict__ cw, const float* __restrict__ cb,
                         const float* __restrict__ dtb, const float* __restrict__ Alog){
    int row = blockIdx.x;            // b*LQ + l
    int l   = row & (LQ-1);
    int ci  = threadIdx.x;           // 0..639
    float4 w = *(const float4*)(cw + ci*4);   // conv_w[ci][0..3]
    const float* src = g_zx + (size_t)row*DPROJ + DINQ + ci;
    float acc = cb[ci];
    acc = fmaf(w.w, src[0], acc);
    if (l >= 1) acc = fmaf(w.z, src[-DPROJ],   acc);
    if (l >= 2) acc = fmaf(w.y, src[-2*DPROJ], acc);
    if (l >= 3) acc = fmaf(w.x, src[-3*DPROJ], acc);
    g_xBC[(size_t)row*CONVD + ci] = acc / (1.f + expf(-acc));   // SiLU
    if (ci < HQ){
        float raw = g_zx[(size_t)row*DPROJ + (DINQ + CONVD) + ci] + dtb[ci];
        float dt  = (raw > 20.f) ? raw : log1pf(expf(raw));     // softplus
        g_dt[(size_t)row*HQ + ci] = dt;
        g_dA[(size_t)row*HQ + ci] = expf(-expf(Alog[ci]) * dt); // exp(dt*A), A=-exp(A_log)
    }
}

// ---------------- SSM scan pass 1: per-chunk local scan, staged 8 steps per barrier ----
// block = (b, h, chunk); 256 threads: p = tid/4, n-quarter = tid%4. Warp w loads step w.
__global__ __launch_bounds__(256) void k_scan1(){
    const int blk = blockIdx.x;
    const int c   = blk & (NCH-1);
    const int bh  = blk >> 5;
    const int h   = bh & (HQ-1);
    const int b   = bh >> 3;
    const int tid = threadIdx.x;
    const int p   = tid >> 2, q = tid & 3;
    const int wid = tid >> 5, lane = tid & 31;

    __shared__ __align__(16) float sX[2][SST][PQ];
    __shared__ __align__(16) float sB[2][SST][NSQ];
    __shared__ __align__(16) float sC[2][SST][NSQ];
    __shared__ float sS[2][SST][2];

    float hs[16];
    #pragma unroll
    for (int j=0;j<16;j++) hs[j]=0.f;

    const int t0 = c*LC;

    // warp-parallel stage loader: warp `wid` loads time-step t0 + st*SST + wid
    auto load_stage = [&](int st, int bf){
        const int t = t0 + st*SST + wid;
        const float* rowp = g_xBC + (size_t)(b*LQ + t)*CONVD;
        if (lane < 16){
            *(float4*)&sX[bf][wid][lane*4] = *(const float4*)(rowp + h*PQ + lane*4);
        }
        {   // B then C: 128 contiguous floats at rowp+DINQ
            float4 v = *(const float4*)(rowp + DINQ + lane*4);
            if (lane < 16) *(float4*)&sB[bf][wid][lane*4]      = v;
            else           *(float4*)&sC[bf][wid][(lane-16)*4] = v;
        }
        if (lane == 16) sS[bf][wid][0] = g_dA[(size_t)(b*LQ + t)*HQ + h];
        if (lane == 17) sS[bf][wid][1] = g_dt[(size_t)(b*LQ + t)*HQ + h];
    };

    load_stage(0, 0);
    __syncthreads();

    float cprod = 1.f;
    #pragma unroll 1
    for (int st=0; st<NSTG; st++){
        const int bf = st & 1;
        if (st+1 < NSTG) load_stage(st+1, bf^1);
        if (tid == 0){   // per-chunk cumulative decay product (8 steps of this stage)
            #pragma unroll
            for (int s=0; s<SST; s++){
                cprod *= sS[bf][s][0];
                g_cum[(size_t)bh*LQ + t0 + st*SST + s] = cprod;
            }
        }
        #pragma unroll
        for (int s=0; s<SST; s++){
            const int t = t0 + st*SST + s;
            const float dA  = sS[bf][s][0];
            const float dtx = sS[bf][s][1] * sX[bf][s][p];
            const float4* pB = (const float4*)&sB[bf][s][q*16];
            const float4* pC = (const float4*)&sC[bf][s][q*16];
            float acc = 0.f;
            #pragma unroll
            for (int v=0; v<4; v++){
                float4 bb = pB[v], cc = pC[v];
                hs[4*v+0] = fmaf(dA, hs[4*v+0], dtx*bb.x); acc = fmaf(hs[4*v+0], cc.x, acc);
                hs[4*v+1] = fmaf(dA, hs[4*v+1], dtx*bb.y); acc = fmaf(hs[4*v+1], cc.y, acc);
                hs[4*v+2] = fmaf(dA, hs[4*v+2], dtx*bb.z); acc = fmaf(hs[4*v+2], cc.z, acc);
                hs[4*v+3] = fmaf(dA, hs[4*v+3], dtx*bb.w); acc = fmaf(hs[4*v+3], cc.w, acc);
            }
            acc += __shfl_xor_sync(0xffffffffu, acc, 1);
            acc += __shfl_xor_sync(0xffffffffu, acc, 2);
            if (q == 0) g_y[(size_t)(b*LQ + t)*DINQ + h*PQ + p] = acc;
        }
        __syncthreads();
    }
    // chunk-final local state
    float4* Fo = (float4*)(g_F + (size_t)blk*(PQ*NSQ) + p*NSQ + q*16);
    Fo[0] = make_float4(hs[0], hs[1], hs[2], hs[3]);
    Fo[1] = make_float4(hs[4], hs[5], hs[6], hs[7]);
    Fo[2] = make_float4(hs[8], hs[9], hs[10], hs[11]);
    Fo[3] = make_float4(hs[12], hs[13], hs[14], hs[15]);
}

// ---------------- chain chunk-start states across chunks (prefetched) ----------------
__global__ __launch_bounds__(256) void k_combine(){
    const int bh  = blockIdx.x;      // 0..15
    const int tid = threadIdx.x;     // owns 16 contiguous state elems
    float hs[16];
    #pragma unroll
    for (int j=0;j<16;j++) hs[j]=0.f;

    size_t base0 = ((size_t)bh*NCH)*(PQ*NSQ) + (size_t)tid*16;
    float4 f[4];
    {
        const float4* Fi = (const float4*)(g_F + base0);
        f[0]=Fi[0]; f[1]=Fi[1]; f[2]=Fi[2]; f[3]=Fi[3];
    }
    float Pt = g_cum[(size_t)bh*LQ + (LC-1)];

    #pragma unroll 1
    for (int c=0; c<NCH; c++){
        size_t base = base0 + (size_t)c*(PQ*NSQ);
        float4* Ho = (float4*)(g_Hs + base);
        Ho[0] = make_float4(hs[0],  hs[1],  hs[2],  hs[3]);
        Ho[1] = make_float4(hs[4],  hs[5],  hs[6],  hs[7]);
        Ho[2] = make_float4(hs[8],  hs[9],  hs[10], hs[11]);
        Ho[3] = make_float4(hs[12], hs[13], hs[14], hs[15]);
        float4 fn[4]; float Ptn = 0.f;
        if (c+1 < NCH){
            const float4* Fi = (const float4*)(g_F + base + (size_t)(PQ*NSQ));
            fn[0]=Fi[0]; fn[1]=Fi[1]; fn[2]=Fi[2]; fn[3]=Fi[3];
            Ptn = g_cum[(size_t)bh*LQ + (c+1)*LC + (LC-1)];
        }
        #pragma unroll
        for (int v=0; v<4; v++){
            hs[4*v+0] = fmaf(Pt, hs[4*v+0], f[v].x);
            hs[4*v+1] = fmaf(Pt, hs[4*v+1], f[v].y);
            hs[4*v+2] = fmaf(Pt, hs[4*v+2], f[v].z);
            hs[4*v+3] = fmaf(Pt, hs[4*v+3], f[v].w);
        }
        if (c+1 < NCH){ f[0]=fn[0]; f[1]=fn[1]; f[2]=fn[2]; f[3]=fn[3]; Pt = Ptn; }
    }
}

// ---------------- scan pass 2: y2 = cum_t * (C_t . h_start) + D * x, staged ----------
__global__ __launch_bounds__(256) void k_scan2(const float* __restrict__ Dparam){
    const int blk = blockIdx.x;
    const int c   = blk & (NCH-1);
    const int bh  = blk >> 5;
    const int h   = bh & (HQ-1);
    const int b   = bh >> 3;
    const int tid = threadIdx.x;
    const int p   = tid >> 2, q = tid & 3;
    const int wid = tid >> 5, lane = tid & 31;

    __shared__ __align__(16) float sC[2][SST][NSQ];
    __shared__ __align__(16) float sX[2][SST][PQ];
    __shared__ float sM[2][SST];

    const float4* Hi = (const float4*)(g_Hs + (size_t)blk*(PQ*NSQ) + p*NSQ + q*16);
    float4 h0 = Hi[0], h1 = Hi[1], h2 = Hi[2], h3 = Hi[3];
    const float Dv = Dparam[h];
    const int t0 = c*LC;

    auto load_stage = [&](int st, int bf){
        const int t = t0 + st*SST + wid;
        const float* rowp = g_xBC + (size_t)(b*LQ + t)*CONVD;
        if (lane < 16)
            *(float4*)&sC[bf][wid][lane*4] = *(const float4*)(rowp + DINQ + NSQ + lane*4);
        else
            *(float4*)&sX[bf][wid][(lane-16)*4] = *(const float4*)(rowp + h*PQ + (lane-16)*4);
        if (lane == 0) sM[bf][wid] = g_cum[(size_t)bh*LQ + t];
    };

    load_stage(0, 0);
    __syncthreads();

    #pragma unroll 1
    for (int st=0; st<NSTG; st++){
        const int bf = st & 1;
        if (st+1 < NSTG) load_stage(st+1, bf^1);
        #pragma unroll
        for (int s=0; s<SST; s++){
            const int t = t0 + st*SST + s;
            const float4* pC = (const float4*)&sC[bf][s][q*16];
            float4 c0=pC[0], c1=pC[1], c2=pC[2], c3=pC[3];
            float acc = 0.f;
            acc = fmaf(h0.x,c0.x,acc); acc = fmaf(h0.y,c0.y,acc); acc = fmaf(h0.z,c0.z,acc); acc = fmaf(h0.w,c0.w,acc);
            acc = fmaf(h1.x,c1.x,acc); acc = fmaf(h1.y,c1.y,acc); acc = fmaf(h1.z,c1.z,acc); acc = fmaf(h1.w,c1.w,acc);
            acc = fmaf(h2.x,c2.x,acc); acc = fmaf(h2.y,c2.y,acc); acc = fmaf(h2.z,c2.z,acc); acc = fmaf(h2.w,c2.w,acc);
            acc = fmaf(h3.x,c3.x,acc); acc = fmaf(h3.y,c3.y,acc); acc = fmaf(h3.z,c3.z,acc); acc = fmaf(h3.w,c3.w,acc);
            acc += __shfl_xor_sync(0xffffffffu, acc, 1);
            acc += __shfl_xor_sync(0xffffffffu, acc, 2);
            if (q == 0){
                float cm = sM[bf][s];
                float xv = sX[bf][s][p];
                g_y2[(size_t)(b*LQ + t)*DINQ + h*PQ + p] = cm*acc + Dv*xv;
            }
        }
        __syncthreads();
    }
}

// ---------------- gate (SiLU(z)) + RMSNorm; sums y1 + y2 ----------------
__global__ __launch_bounds__(512) void k_gatenorm(const float* __restrict__ nw){
    int row = blockIdx.x;
    int tid = threadIdx.x;
    float y = g_y[(size_t)row*DINQ + tid] + g_y2[(size_t)row*DINQ + tid];
    float z = g_zx[(size_t)row*DPROJ + tid];
    float v = y * (z / (1.f + expf(-z)));
    float ss = v*v;
    #pragma unroll
    for (int o=16;o;o>>=1) ss += __shfl_xor_sync(0xffffffffu, ss, o);
    __shared__ float red[16];
    if ((tid & 31) == 0) red[tid>>5] = ss;
    __syncthreads();
    if (tid < 32){
        float t = (tid < 16) ? red[tid] : 0.f;
        #pragma unroll
        for (int o=8;o;o>>=1) t += __shfl_xor_sync(0xffffffffu, t, o);
        if (tid == 0) red[0] = t;
    }
    __syncthreads();
    float r = rsqrtf(red[0]*(1.f/DINQ) + 1e-5f);
    g_y[(size_t)row*DINQ + tid] = v * r * nw[tid];
}

// ---------------- pooling: (mean_l + max_l) * 0.5 ----------------
__global__ void k_pool(){
    int b = blockIdx.x, d = threadIdx.x;
    const float* base = g_x + (size_t)b*LQ*DQ + d;
    float s = 0.f, m = -3.4e38f;
    #pragma unroll 8
    for (int l=0; l<LQ; l++){
        float v = base[(size_t)l*DQ];
        s += v; m = fmaxf(m, v);
    }
    g_pool[b*DQ + d] = (s*(1.f/LQ) + m)*0.5f;
}

// ---------------- classification head (single block) ----------------
__global__ __launch_bounds__(256) void k_head(const float* __restrict__ pw, const float* __restrict__ pb,
                                              const float* __restrict__ c1w, const float* __restrict__ c1b,
                                              const float* __restrict__ c2w, const float* __restrict__ c2b,
                                              float* __restrict__ out){
    __shared__ __align__(16) float sp[BQ*DQ];
    __shared__ __align__(16) float h1[BQ*DQ];
    __shared__ __align__(16) float h2[BQ*128];
    int tid = threadIdx.x;
    for (int i=tid; i<BQ*DQ; i+=256) sp[i] = g_pool[i];
    __syncthreads();
    for (int i=tid; i<BQ*DQ; i+=256){
        int b = i >> 8, o = i & 255;
        const float4* xr = (const float4*)(sp + b*DQ);
        const float4* wr = (const float4*)(pw + (size_t)o*DQ);
        float a = pb[o];
        #pragma unroll 8
        for (int k=0; k<DQ/4; k++){
            float4 xv = xr[k], wv = wr[k];
            a = fmaf(xv.x,wv.x,a); a = fmaf(xv.y,wv.y,a);
            a = fmaf(xv.z,wv.z,a); a = fmaf(xv.w,wv.w,a);
        }
        h1[i] = geluf(a);
    }
    __syncthreads();
    {
        int b = tid >> 7, o = tid & 127;
        const float4* xr = (const float4*)(h1 + b*DQ);
        const float4* wr = (const float4*)(c1w + (size_t)o*DQ);
        float a = c1b[o];
        #pragma unroll 8
        for (int k=0; k<DQ/4; k++){
            float4 xv = xr[k], wv = wr[k];
            a = fmaf(xv.x,wv.x,a); a = fmaf(xv.y,wv.y,a);
            a = fmaf(xv.z,wv.z,a); a = fmaf(xv.w,wv.w,a);
        }
        h2[tid] = geluf(a);
    }
    __syncthreads();
    if (tid < 4){
        int b = tid >> 1, o = tid & 1;
        const float* xr = h2 + b*128;
        const float* wr = c2w + o*128;
        float a = c2b[o];
        #pragma unroll 8
        for (int k=0; k<128; k++) a = fmaf(xr[k], wr[k], a);
        out[b*2 + o] = a;
    }
}

// ---------------- launcher ----------------
extern "C" void kernel_launch(void* const* d_in, const int* in_sizes, int n_in,
                              void* d_out, int out_size){
    (void)in_sizes; (void)n_in; (void)out_size;
    const int*   ids  = (const int*)  d_in[0];
    const float* emb  = (const float*)d_in[1];
    const float* pos  = (const float*)d_in[2];
    const float* Win  = (const float*)d_in[3];
    const float* cw   = (const float*)d_in[4];
    const float* cb   = (const float*)d_in[5];
    const float* dtb  = (const float*)d_in[6];
    const float* Alog = (const float*)d_in[7];
    const float* Dpar = (const float*)d_in[8];
    const float* nw   = (const float*)d_in[9];
    const float* Wout = (const float*)d_in[10];
    const float* pw   = (const float*)d_in[11];
    const float* pb   = (const float*)d_in[12];
    const float* c1w  = (const float*)d_in[13];
    const float* c1b  = (const float*)d_in[14];
    const float* c2w  = (const float*)d_in[15];
    const float* c2b  = (const float*)d_in[16];
    float* out = (float*)d_out;

    k_embed<<<BQ*LQ, DQ>>>(ids, emb, pos);
    for (int i=0; i<NLQ; i++){
        k_gemm_in <<<dim3((DPROJ+63)/64, (BQ*LQ)/64), 256>>>(Win + (size_t)i*DPROJ*DQ);
        k_convdt  <<<BQ*LQ, CONVD>>>(cw + (size_t)i*CONVD*4, cb + (size_t)i*CONVD,
                                     dtb + (size_t)i*HQ, Alog + (size_t)i*HQ);
        k_scan1   <<<BQ*HQ*NCH, 256>>>();
        k_combine <<<BQ*HQ, 256>>>();
        k_scan2   <<<BQ*HQ*NCH, 256>>>(Dpar + (size_t)i*HQ);
        k_gatenorm<<<BQ*LQ, DINQ>>>(nw + (size_t)i*DINQ);
        k_gemm_out<<<dim3(DQ/64, (BQ*LQ)/64), 256>>>(Wout + (size_t)i*DQ*DINQ);
    }
    k_pool<<<BQ, DQ>>>();
    k_head<<<1, 256>>>(pw, pb, c1w, c1b, c2w, c2b, out);
}

// round 5
// speedup vs baseline: 1.2533x; 1.0941x over previous
#include <cuda_runtime.h>
#include <math.h>

// ---------------- problem constants ----------------
#define BQ     2
#define LQ     1024
#define DQ     256
#define NLQ    4
#define DINQ   512
#define HQ     8
#define PQ     64
#define NSQ    64
#define CONVD  640           // DIN + 2*NSTATE
#define DPROJ  1160          // 2*DIN + 2*NSTATE + H
#define NCH    32            // chunks for scan
#define LC     32            // chunk length (LQ / NCH)
#define SST    8             // time-steps staged per barrier
#define NSTG   (LC/SST)      // stages per chunk

// ---------------- scratch (device globals; no allocation) ----------------
static __device__ float g_x  [BQ*LQ*DQ];
static __device__ float g_zx [BQ*LQ*DPROJ];
static __device__ float g_xBC[BQ*LQ*CONVD];
static __device__ float g_dt [BQ*LQ*HQ];
static __device__ float g_dA [BQ*LQ*HQ];
static __device__ float g_cum[BQ*HQ*LQ];
static __device__ float g_y  [BQ*LQ*DINQ];
static __device__ float g_y2 [BQ*LQ*DINQ];
static __device__ float g_F  [BQ*HQ*NCH*PQ*NSQ];
static __device__ float g_Hs [BQ*HQ*NCH*PQ*NSQ];
static __device__ float g_pool[BQ*DQ];

__device__ __forceinline__ float geluf(float x){
    return 0.5f * x * (1.0f + erff(x * 0.7071067811865476f));
}

// ---------------- embedding ----------------
__global__ void k_embed(const int* __restrict__ ids, const float* __restrict__ emb,
                        const float* __restrict__ pos){
    int row = blockIdx.x;            // b*LQ + l
    int l   = row & (LQ-1);
    int d   = threadIdx.x;
    g_x[(size_t)row*DQ + d] = emb[(size_t)ids[row]*DQ + d] + pos[(size_t)l*DQ + d];
}

// ================= GEMM 128x64 (prefetch-pipelined), C[m,n] = sum_k A[m,k]*B[n,k] ======
template<int M, int N, int K, bool ACC>
__device__ __forceinline__ void gemm128(const float* __restrict__ A,
                                        const float* __restrict__ Bw,
                                        float* __restrict__ Cc){
    constexpr int BM=128, BN=64, BK=16;
    __shared__ __align__(16) float As[2][BK][BM];
    __shared__ __align__(16) float Bs[2][BK][BN];
    const int tid = threadIdx.x;
    const int bm  = blockIdx.y * BM;
    const int bn  = blockIdx.x * BN;
    // load mapping
    const int alr = tid & 127;         // A row in tile
    const int alc = (tid >> 7) * 8;    // A k-offset (0 or 8)
    const int blr = tid & 63;          // B row in tile
    const int blc = (tid >> 6) * 4;    // B k-offset (0,4,8,12)
    // compute mapping: 16x16 thread grid, 8x4 micro-tile
    const int tr  = (tid >> 4) * 8;
    const int tc  = (tid & 15) * 4;

    const bool bvalid = (N % BN == 0) || (bn + blr < N);
    const float* Aptr = A  + (size_t)(bm + alr)*K + alc;
    const float* Bptr = Bw + (size_t)(bn + blr)*K + blc;

    float acc[8][4];
    #pragma unroll
    for (int m=0;m<8;m++)
        #pragma unroll
        for (int n=0;n<4;n++) acc[m][n]=0.f;

    float4 ra0, ra1, rb0;
    auto ldg = [&](int k0){
        ra0 = *(const float4*)(Aptr + k0);
        ra1 = *(const float4*)(Aptr + k0 + 4);
        rb0 = make_float4(0.f,0.f,0.f,0.f);
        if (bvalid) rb0 = *(const float4*)(Bptr + k0);
    };
    auto sts = [&](int buf){
        As[buf][alc+0][alr]=ra0.x; As[buf][alc+1][alr]=ra0.y;
        As[buf][alc+2][alr]=ra0.z; As[buf][alc+3][alr]=ra0.w;
        As[buf][alc+4][alr]=ra1.x; As[buf][alc+5][alr]=ra1.y;
        As[buf][alc+6][alr]=ra1.z; As[buf][alc+7][alr]=ra1.w;
        Bs[buf][blc+0][blr]=rb0.x; Bs[buf][blc+1][blr]=rb0.y;
        Bs[buf][blc+2][blr]=rb0.z; Bs[buf][blc+3][blr]=rb0.w;
    };

    ldg(0); sts(0);
    __syncthreads();
    constexpr int NK = K/BK;
    #pragma unroll 1
    for (int kt=0; kt<NK; kt++){
        if (kt+1 < NK) ldg((kt+1)*BK);
        const int cur = kt & 1;
        #pragma unroll
        for (int kk=0; kk<BK; kk++){
            float4 a0 = *(const float4*)&As[cur][kk][tr];
            float4 a1 = *(const float4*)&As[cur][kk][tr+4];
            float4 b  = *(const float4*)&Bs[cur][kk][tc];
            float am[8] = {a0.x,a0.y,a0.z,a0.w,a1.x,a1.y,a1.z,a1.w};
            float bn4[4] = {b.x,b.y,b.z,b.w};
            #pragma unroll
            for (int m=0;m<8;m++)
                #pragma unroll
                for (int n=0;n<4;n++)
                    acc[m][n] = fmaf(am[m], bn4[n], acc[m][n]);
        }
        if (kt+1 < NK) sts((kt+1) & 1);
        __syncthreads();
    }
    #pragma unroll
    for (int m=0;m<8;m++){
        int row = bm + tr + m;
        #pragma unroll
        for (int n=0;n<4;n++){
            int col = bn + tc + n;
            if (N % BN == 0 || col < N){
                size_t idx = (size_t)row*N + col;
                if (ACC) Cc[idx] += acc[m][n];
                else     Cc[idx]  = acc[m][n];
            }
        }
    }
}

// ================= GEMM 64x64 (prefetch-pipelined) =================
template<int M, int N, int K, bool ACC>
__device__ __forceinline__ void gemm64(const float* __restrict__ A,
                                       const float* __restrict__ Bw,
                                       float* __restrict__ Cc){
    constexpr int BM=64, BN=64, BK=16;
    __shared__ __align__(16) float As[2][BK][BM];
    __shared__ __align__(16) float Bs[2][BK][BN];
    const int tid = threadIdx.x;
    const int bm  = blockIdx.y * BM;
    const int bn  = blockIdx.x * BN;
    const int lr  = tid & 63;
    const int lc  = (tid >> 6) * 4;
    const int tr  = (tid >> 4) * 4;
    const int tc  = (tid & 15) * 4;

    const bool bvalid = (N % BN == 0) || (bn + lr < N);
    const float* Aptr = A  + (size_t)(bm + lr)*K + lc;
    const float* Bptr = Bw + (size_t)(bn + lr)*K + lc;

    float acc[4][4];
    #pragma unroll
    for (int m=0;m<4;m++)
        #pragma unroll
        for (int n=0;n<4;n++) acc[m][n]=0.f;

    float4 ra, rb;
    auto ldg = [&](int k0){
        ra = *(const float4*)(Aptr + k0);
        rb = make_float4(0.f,0.f,0.f,0.f);
        if (bvalid) rb = *(const float4*)(Bptr + k0);
    };
    auto sts = [&](int buf){
        As[buf][lc+0][lr]=ra.x; As[buf][lc+1][lr]=ra.y;
        As[buf][lc+2][lr]=ra.z; As[buf][lc+3][lr]=ra.w;
        Bs[buf][lc+0][lr]=rb.x; Bs[buf][lc+1][lr]=rb.y;
        Bs[buf][lc+2][lr]=rb.z; Bs[buf][lc+3][lr]=rb.w;
    };

    ldg(0); sts(0);
    __syncthreads();
    constexpr int NK = K/BK;
    #pragma unroll 1
    for (int kt=0; kt<NK; kt++){
        if (kt+1 < NK) ldg((kt+1)*BK);
        const int cur = kt & 1;
        #pragma unroll
        for (int kk=0; kk<BK; kk++){
            float4 a = *(const float4*)&As[cur][kk][tr];
            float4 b = *(const float4*)&Bs[cur][kk][tc];
            float am[4] = {a.x,a.y,a.z,a.w};
            float bn4[4] = {b.x,b.y,b.z,b.w};
            #pragma unroll
            for (int m=0;m<4;m++)
                #pragma unroll
                for (int n=0;n<4;n++)
                    acc[m][n] = fmaf(am[m], bn4[n], acc[m][n]);
        }
        if (kt+1 < NK) sts((kt+1) & 1);
        __syncthreads();
    }
    #pragma unroll
    for (int m=0;m<4;m++){
        int row = bm + tr + m;
        #pragma unroll
        for (int n=0;n<4;n++){
            int col = bn + tc + n;
            if (N % BN == 0 || col < N){
                size_t idx = (size_t)row*N + col;
                if (ACC) Cc[idx] += acc[m][n];
                else     Cc[idx]  = acc[m][n];
            }
        }
    }
}

__global__ __launch_bounds__(256) void k_gemm_in(const float* __restrict__ W){
    gemm128<BQ*LQ, DPROJ, DQ, false>(g_x, W, g_zx);
}
__global__ __launch_bounds__(256) void k_gemm_out(const float* __restrict__ W){
    gemm64<BQ*LQ, DQ, DINQ, true>(g_y, W, g_x);
}

// ---------------- depthwise causal conv + SiLU, and dt / dA ----------------
__global__ void k_convdt(const float* __restrict__ cw, const float* __restrict__ cb,
                         const float* __restrict__ dtb, const float* __restrict__ Alog){
    int row = blockIdx.x;            // b*LQ + l
    int l   = row & (LQ-1);
    int ci  = threadIdx.x;           // 0..639
    float4 w = *(const float4*)(cw + ci*4);   // conv_w[ci][0..3]
    const float* src = g_zx + (size_t)row*DPROJ + DINQ + ci;
    float acc = cb[ci];
    acc = fmaf(w.w, src[0], acc);
    if (l >= 1) acc = fmaf(w.z, src[-DPROJ],   acc);
    if (l >= 2) acc = fmaf(w.y, src[-2*DPROJ], acc);
    if (l >= 3) acc = fmaf(w.x, src[-3*DPROJ], acc);
    g_xBC[(size_t)row*CONVD + ci] = acc / (1.f + expf(-acc));   // SiLU
    if (ci < HQ){
        float raw = g_zx[(size_t)row*DPROJ + (DINQ + CONVD) + ci] + dtb[ci];
        float dt  = (raw > 20.f) ? raw : log1pf(expf(raw));     // softplus
        g_dt[(size_t)row*HQ + ci] = dt;
        g_dA[(size_t)row*HQ + ci] = expf(-expf(Alog[ci]) * dt); // exp(dt*A), A=-exp(A_log)
    }
}

// ---------------- SSM scan pass 1: staged + LDG/STS split pipeline ----------------
// block = (b, h, chunk); 256 threads: p = tid/4, n-quarter = tid%4. Warp w loads step w.
__global__ __launch_bounds__(256) void k_scan1(){
    const int blk = blockIdx.x;
    const int c   = blk & (NCH-1);
    const int bh  = blk >> 5;
    const int h   = bh & (HQ-1);
    const int b   = bh >> 3;
    const int tid = threadIdx.x;
    const int p   = tid >> 2, q = tid & 3;
    const int wid = tid >> 5, lane = tid & 31;

    __shared__ __align__(16) float sX[2][SST][PQ];
    __shared__ __align__(16) float sB[2][SST][NSQ];
    __shared__ __align__(16) float sC[2][SST][NSQ];
    __shared__ float sS[2][SST][2];

    float hs[16];
    #pragma unroll
    for (int j=0;j<16;j++) hs[j]=0.f;

    const int t0 = c*LC;

    float4 rX, rBC; float rS = 0.f;
    auto ldg_stage = [&](int st){
        const int t = t0 + st*SST + wid;
        const float* rowp = g_xBC + (size_t)(b*LQ + t)*CONVD;
        if (lane < 16) rX = *(const float4*)(rowp + h*PQ + lane*4);
        rBC = *(const float4*)(rowp + DINQ + lane*4);   // covers B (lane<16) and C (lane>=16)
        if (lane == 16) rS = g_dA[(size_t)(b*LQ + t)*HQ + h];
        if (lane == 17) rS = g_dt[(size_t)(b*LQ + t)*HQ + h];
    };
    auto sts_stage = [&](int bf){
        if (lane < 16){
            *(float4*)&sX[bf][wid][lane*4] = rX;
            *(float4*)&sB[bf][wid][lane*4] = rBC;
        } else {
            *(float4*)&sC[bf][wid][(lane-16)*4] = rBC;
        }
        if (lane == 16) sS[bf][wid][0] = rS;
        if (lane == 17) sS[bf][wid][1] = rS;
    };

    ldg_stage(0); sts_stage(0);
    __syncthreads();

    float cprod = 1.f;
    #pragma unroll 1
    for (int st=0; st<NSTG; st++){
        const int bf = st & 1;
        if (st+1 < NSTG) ldg_stage(st+1);
        if (tid == 0){   // per-chunk cumulative decay product
            #pragma unroll
            for (int s=0; s<SST; s++){
                cprod *= sS[bf][s][0];
                g_cum[(size_t)bh*LQ + t0 + st*SST + s] = cprod;
            }
        }
        #pragma unroll
        for (int s=0; s<SST; s++){
            const int t = t0 + st*SST + s;
            const float dA  = sS[bf][s][0];
            const float dtx = sS[bf][s][1] * sX[bf][s][p];
            const float4* pB = (const float4*)&sB[bf][s][q*16];
            const float4* pC = (const float4*)&sC[bf][s][q*16];
            float acc = 0.f;
            #pragma unroll
            for (int v=0; v<4; v++){
                float4 bb = pB[v], cc = pC[v];
                hs[4*v+0] = fmaf(dA, hs[4*v+0], dtx*bb.x); acc = fmaf(hs[4*v+0], cc.x, acc);
                hs[4*v+1] = fmaf(dA, hs[4*v+1], dtx*bb.y); acc = fmaf(hs[4*v+1], cc.y, acc);
                hs[4*v+2] = fmaf(dA, hs[4*v+2], dtx*bb.z); acc = fmaf(hs[4*v+2], cc.z, acc);
                hs[4*v+3] = fmaf(dA, hs[4*v+3], dtx*bb.w); acc = fmaf(hs[4*v+3], cc.w, acc);
            }
            acc += __shfl_xor_sync(0xffffffffu, acc, 1);
            acc += __shfl_xor_sync(0xffffffffu, acc, 2);
            if (q == 0) g_y[(size_t)(b*LQ + t)*DINQ + h*PQ + p] = acc;
        }
        if (st+1 < NSTG) sts_stage((st+1) & 1);
        __syncthreads();
    }
    // chunk-final local state
    float4* Fo = (float4*)(g_F + (size_t)blk*(PQ*NSQ) + p*NSQ + q*16);
    Fo[0] = make_float4(hs[0], hs[1], hs[2], hs[3]);
    Fo[1] = make_float4(hs[4], hs[5], hs[6], hs[7]);
    Fo[2] = make_float4(hs[8], hs[9], hs[10], hs[11]);
    Fo[3] = make_float4(hs[12], hs[13], hs[14], hs[15]);
}

// ---------------- chain chunk-start states across chunks (prefetched) ----------------
__global__ __launch_bounds__(256) void k_combine(){
    const int bh  = blockIdx.x;      // 0..15
    const int tid = threadIdx.x;     // owns 16 contiguous state elems
    float hs[16];
    #pragma unroll
    for (int j=0;j<16;j++) hs[j]=0.f;

    size_t base0 = ((size_t)bh*NCH)*(PQ*NSQ) + (size_t)tid*16;
    float4 f[4];
    {
        const float4* Fi = (const float4*)(g_F + base0);
        f[0]=Fi[0]; f[1]=Fi[1]; f[2]=Fi[2]; f[3]=Fi[3];
    }
    float Pt = g_cum[(size_t)bh*LQ + (LC-1)];

    #pragma unroll 1
    for (int c=0; c<NCH; c++){
        size_t base = base0 + (size_t)c*(PQ*NSQ);
        float4* Ho = (float4*)(g_Hs + base);
        Ho[0] = make_float4(hs[0],  hs[1],  hs[2],  hs[3]);
        Ho[1] = make_float4(hs[4],  hs[5],  hs[6],  hs[7]);
        Ho[2] = make_float4(hs[8],  hs[9],  hs[10], hs[11]);
        Ho[3] = make_float4(hs[12], hs[13], hs[14], hs[15]);
        float4 fn[4]; float Ptn = 0.f;
        if (c+1 < NCH){
            const float4* Fi = (const float4*)(g_F + base + (size_t)(PQ*NSQ));
            fn[0]=Fi[0]; fn[1]=Fi[1]; fn[2]=Fi[2]; fn[3]=Fi[3];
            Ptn = g_cum[(size_t)bh*LQ + (c+1)*LC + (LC-1)];
        }
        #pragma unroll
        for (int v=0; v<4; v++){
            hs[4*v+0] = fmaf(Pt, hs[4*v+0], f[v].x);
            hs[4*v+1] = fmaf(Pt, hs[4*v+1], f[v].y);
            hs[4*v+2] = fmaf(Pt, hs[4*v+2], f[v].z);
            hs[4*v+3] = fmaf(Pt, hs[4*v+3], f[v].w);
        }
        if (c+1 < NCH){ f[0]=fn[0]; f[1]=fn[1]; f[2]=fn[2]; f[3]=fn[3]; Pt = Ptn; }
    }
}

// ---------------- scan pass 2: y2 = cum_t * (C_t . h_start) + D * x, pipelined -------
__global__ __launch_bounds__(256) void k_scan2(const float* __restrict__ Dparam){
    const int blk = blockIdx.x;
    const int c   = blk & (NCH-1);
    const int bh  = blk >> 5;
    const int h   = bh & (HQ-1);
    const int b   = bh >> 3;
    const int tid = threadIdx.x;
    const int p   = tid >> 2, q = tid & 3;
    const int wid = tid >> 5, lane = tid & 31;

    __shared__ __align__(16) float sC[2][SST][NSQ];
    __shared__ __align__(16) float sX[2][SST][PQ];
    __shared__ float sM[2][SST];

    const float4* Hi = (const float4*)(g_Hs + (size_t)blk*(PQ*NSQ) + p*NSQ + q*16);
    float4 h0 = Hi[0], h1 = Hi[1], h2 = Hi[2], h3 = Hi[3];
    const float Dv = Dparam[h];
    const int t0 = c*LC;

    float4 rCX; float rM = 0.f;
    auto ldg_stage = [&](int st){
        const int t = t0 + st*SST + wid;
        const float* rowp = g_xBC + (size_t)(b*LQ + t)*CONVD;
        if (lane < 16) rCX = *(const float4*)(rowp + DINQ + NSQ + lane*4);
        else           rCX = *(const float4*)(rowp + h*PQ + (lane-16)*4);
        if (lane == 0) rM = g_cum[(size_t)bh*LQ + t];
    };
    auto sts_stage = [&](int bf){
        if (lane < 16) *(float4*)&sC[bf][wid][lane*4]      = rCX;
        else           *(float4*)&sX[bf][wid][(lane-16)*4] = rCX;
        if (lane == 0) sM[bf][wid] = rM;
    };

    ldg_stage(0); sts_stage(0);
    __syncthreads();

    #pragma unroll 1
    for (int st=0; st<NSTG; st++){
        const int bf = st & 1;
        if (st+1 < NSTG) ldg_stage(st+1);
        #pragma unroll
        for (int s=0; s<SST; s++){
            const int t = t0 + st*SST + s;
            const float4* pC = (const float4*)&sC[bf][s][q*16];
            float4 c0=pC[0], c1=pC[1], c2=pC[2], c3=pC[3];
            float acc = 0.f;
            acc = fmaf(h0.x,c0.x,acc); acc = fmaf(h0.y,c0.y,acc); acc = fmaf(h0.z,c0.z,acc); acc = fmaf(h0.w,c0.w,acc);
            acc = fmaf(h1.x,c1.x,acc); acc = fmaf(h1.y,c1.y,acc); acc = fmaf(h1.z,c1.z,acc); acc = fmaf(h1.w,c1.w,acc);
            acc = fmaf(h2.x,c2.x,acc); acc = fmaf(h2.y,c2.y,acc); acc = fmaf(h2.z,c2.z,acc); acc = fmaf(h2.w,c2.w,acc);
            acc = fmaf(h3.x,c3.x,acc); acc = fmaf(h3.y,c3.y,acc); acc = fmaf(h3.z,c3.z,acc); acc = fmaf(h3.w,c3.w,acc);
            acc += __shfl_xor_sync(0xffffffffu, acc, 1);
            acc += __shfl_xor_sync(0xffffffffu, acc, 2);
            if (q == 0){
                float cm = sM[bf][s];
                float xv = sX[bf][s][p];
                g_y2[(size_t)(b*LQ + t)*DINQ + h*PQ + p] = cm*acc + Dv*xv;
            }
        }
        if (st+1 < NSTG) sts_stage((st+1) & 1);
        __syncthreads();
    }
}

// ---------------- gate (SiLU(z)) + RMSNorm; sums y1 + y2 ----------------
__global__ __launch_bounds__(512) void k_gatenorm(const float* __restrict__ nw){
    int row = blockIdx.x;
    int tid = threadIdx.x;
    float y = g_y[(size_t)row*DINQ + tid] + g_y2[(size_t)row*DINQ + tid];
    float z = g_zx[(size_t)row*DPROJ + tid];
    float v = y * (z / (1.f + expf(-z)));
    float ss = v*v;
    #pragma unroll
    for (int o=16;o;o>>=1) ss += __shfl_xor_sync(0xffffffffu, ss, o);
    __shared__ float red[16];
    if ((tid & 31) == 0) red[tid>>5] = ss;
    __syncthreads();
    if (tid < 32){
        float t = (tid < 16) ? red[tid] : 0.f;
        #pragma unroll
        for (int o=8;o;o>>=1) t += __shfl_xor_sync(0xffffffffu, t, o);
        if (tid == 0) red[0] = t;
    }
    __syncthreads();
    float r = rsqrtf(red[0]*(1.f/DINQ) + 1e-5f);
    g_y[(size_t)row*DINQ + tid] = v * r * nw[tid];
}

// ---------------- pooling: (mean_l + max_l) * 0.5 ----------------
__global__ void k_pool(){
    int b = blockIdx.x, d = threadIdx.x;
    const float* base = g_x + (size_t)b*LQ*DQ + d;
    float s = 0.f, m = -3.4e38f;
    #pragma unroll 8
    for (int l=0; l<LQ; l++){
        float v = base[(size_t)l*DQ];
        s += v; m = fmaxf(m, v);
    }
    g_pool[b*DQ + d] = (s*(1.f/LQ) + m)*0.5f;
}

// ---------------- classification head (single block) ----------------
__global__ __launch_bounds__(256) void k_head(const float* __restrict__ pw, const float* __restrict__ pb,
                                              const float* __restrict__ c1w, const float* __restrict__ c1b,
                                              const float* __restrict__ c2w, const float* __restrict__ c2b,
                                              float* __restrict__ out){
    __shared__ __align__(16) float sp[BQ*DQ];
    __shared__ __align__(16) float h1[BQ*DQ];
    __shared__ __align__(16) float h2[BQ*128];
    int tid = threadIdx.x;
    for (int i=tid; i<BQ*DQ; i+=256) sp[i] = g_pool[i];
    __syncthreads();
    for (int i=tid; i<BQ*DQ; i+=256){
        int b = i >> 8, o = i & 255;
        const float4* xr = (const float4*)(sp + b*DQ);
        const float4* wr = (const float4*)(pw + (size_t)o*DQ);
        float a = pb[o];
        #pragma unroll 8
        for (int k=0; k<DQ/4; k++){
            float4 xv = xr[k], wv = wr[k];
            a = fmaf(xv.x,wv.x,a); a = fmaf(xv.y,wv.y,a);
            a = fmaf(xv.z,wv.z,a); a = fmaf(xv.w,wv.w,a);
        }
        h1[i] = geluf(a);
    }
    __syncthreads();
    {
        int b = tid >> 7, o = tid & 127;
        const float4* xr = (const float4*)(h1 + b*DQ);
        const float4* wr = (const float4*)(c1w + (size_t)o*DQ);
        float a = c1b[o];
        #pragma unroll 8
        for (int k=0; k<DQ/4; k++){
            float4 xv = xr[k], wv = wr[k];
            a = fmaf(xv.x,wv.x,a); a = fmaf(xv.y,wv.y,a);
            a = fmaf(xv.z,wv.z,a); a = fmaf(xv.w,wv.w,a);
        }
        h2[tid] = geluf(a);
    }
    __syncthreads();
    if (tid < 4){
        int b = tid >> 1, o = tid & 1;
        const float* xr = h2 + b*128;
        const float* wr = c2w + o*128;
        float a = c2b[o];
        #pragma unroll 8
        for (int k=0; k<128; k++) a = fmaf(xr[k], wr[k], a);
        out[b*2 + o] = a;
    }
}

// ---------------- launcher ----------------
extern "C" void kernel_launch(void* const* d_in, const int* in_sizes, int n_in,
                              void* d_out, int out_size){
    (void)in_sizes; (void)n_in; (void)out_size;
    const int*   ids  = (const int*)  d_in[0];
    const float* emb  = (const float*)d_in[1];
    const float* pos  = (const float*)d_in[2];
    const float* Win  = (const float*)d_in[3];
    const float* cw   = (const float*)d_in[4];
    const float* cb   = (const float*)d_in[5];
    const float* dtb  = (const float*)d_in[6];
    const float* Alog = (const float*)d_in[7];
    const float* Dpar = (const float*)d_in[8];
    const float* nw   = (const float*)d_in[9];
    const float* Wout = (const float*)d_in[10];
    const float* pw   = (const float*)d_in[11];
    const float* pb   = (const float*)d_in[12];
    const float* c1w  = (const float*)d_in[13];
    const float* c1b  = (const float*)d_in[14];
    const float* c2w  = (const float*)d_in[15];
    const float* c2b  = (const float*)d_in[16];
    float* out = (float*)d_out;

    k_embed<<<BQ*LQ, DQ>>>(ids, emb, pos);
    for (int i=0; i<NLQ; i++){
        k_gemm_in <<<dim3((DPROJ+63)/64, (BQ*LQ)/128), 256>>>(Win + (size_t)i*DPROJ*DQ);
        k_convdt  <<<BQ*LQ, CONVD>>>(cw + (size_t)i*CONVD*4, cb + (size_t)i*CONVD,
                                     dtb + (size_t)i*HQ, Alog + (size_t)i*HQ);
        k_scan1   <<<BQ*HQ*NCH, 256>>>();
        k_combine <<<BQ*HQ, 256>>>();
        k_scan2   <<<BQ*HQ*NCH, 256>>>(Dpar + (size_t)i*HQ);
        k_gatenorm<<<BQ*LQ, DINQ>>>(nw + (size_t)i*DINQ);
        k_gemm_out<<<dim3(DQ/64, (BQ*LQ)/64), 256>>>(Wout + (size_t)i*DQ*DINQ);
    }
    k_pool<<<BQ, DQ>>>();
    k_head<<<1, 256>>>(pw, pb, c1w, c1b, c2w, c2b, out);
}